// round 6
// baseline (speedup 1.0000x reference)
#include <cuda_runtime.h>
#include <math.h>

// ---------------------------------------------------------------------------
// PoseConvLSTM: 2 ConvLSTM layers (hc=32, hc=64), 3x3 SAME conv, T=128 steps
// on 64x64 grids, then FC. fp32 with packed fma.rn.f32x2 (sm_103a FFMA2).
// R6: cin-loop unroll 2 with row-staged smem weight reads (no LDG staging)
// to overlap LDS latency with FMA issue; weights remain SMEM-resident.
// ---------------------------------------------------------------------------

#define NPIX 4096
#define TT 128

typedef unsigned long long ull;

// ----- scratch -----
__device__ float g_ys1[TT * 32 * NPIX];
__device__ float g_ys2[TT * 64 * NPIX];
__device__ float g_c1[32 * NPIX];
__device__ float g_c2[64 * NPIX];
__device__ float g_zerobuf[64 * NPIX];
__device__ __align__(16) float g_w1p[32 * 35 * 36];
__device__ __align__(16) float g_w2p[64 * 96 * 36];
__device__ float g_fcpart[64 * TT * 6];

__device__ __forceinline__ float sigmf(float x) {
    return 1.0f / (1.0f + __expf(-x));
}
__device__ __forceinline__ float tanh_f(float x) {
    return 1.0f - 2.0f / (__expf(2.0f * x) + 1.0f);
}

// ----- f32x2 helpers -----
__device__ __forceinline__ ull pack2(float lo, float hi) {
    ull r;
    asm("mov.b64 %0, {%1, %2};" : "=l"(r) : "f"(lo), "f"(hi));
    return r;
}
__device__ __forceinline__ ull dup2(float v) {
    ull r;
    asm("mov.b64 %0, {%1, %1};" : "=l"(r) : "f"(v));
    return r;
}
__device__ __forceinline__ void unpack2(ull p, float& lo, float& hi) {
    asm("mov.b64 {%0, %1}, %2;" : "=f"(lo), "=f"(hi) : "l"(p));
}
__device__ __forceinline__ ull ffma2(ull a, ull b, ull c) {
    ull d;
    asm("fma.rn.f32x2 %0, %1, %2, %3;" : "=l"(d) : "l"(a), "l"(b), "l"(c));
    return d;
}
__device__ __forceinline__ unsigned smem_u32(const void* p) {
    return (unsigned)__cvta_generic_to_shared(p);
}
__device__ __forceinline__ void cp16(unsigned s, const void* g) {
    asm volatile("cp.async.cg.shared.global [%0], [%1], 16;"
                 :: "r"(s), "l"(g) : "memory");
}
__device__ __forceinline__ void cp_commit() {
    asm volatile("cp.async.commit_group;" ::: "memory");
}
__device__ __forceinline__ void cp_wait0() {
    asm volatile("cp.async.wait_group 0;" ::: "memory");
}

// ----- merged setup (1 launch) -----
__global__ void setup_kernel(const float* __restrict__ w1,
                             const float* __restrict__ w2,
                             float* __restrict__ w1p, float* __restrict__ w2p,
                             float* __restrict__ c1, float* __restrict__ c2,
                             float* __restrict__ zb) {
    int i = blockIdx.x * blockDim.x + threadIdx.x;
    const int N_C1 = 32 * NPIX;
    const int N_C2 = 64 * NPIX;
    const int N_W1 = 32 * 35 * 36;
    const int N_W2 = 64 * 96 * 36;
    if (i < N_C1) { c1[i] = 0.0f; return; }
    i -= N_C1;
    if (i < N_C2) { c2[i] = 0.0f; return; }
    i -= N_C2;
    if (i < N_C2) { zb[i] = 0.0f; return; }
    i -= N_C2;
    if (i < N_W1) {
        int g = i & 3; int r = i >> 2;
        int t = r % 9; r /= 9;
        int cin = r % 35; int co = r / 35;
        w1p[i] = w1[((g * 32 + co) * 35 + cin) * 9 + t];
        return;
    }
    i -= N_W1;
    if (i < N_W2) {
        int g = i & 3; int r = i >> 2;
        int t = r % 9; r /= 9;
        int cin = r % 96; int co = r / 96;
        w2p[i] = w2[((g * 64 + co) * 96 + cin) * 9 + t];
        return;
    }
}

// ----- fused ConvLSTM step, smem-staged weights -----
template <int HC, int CIN, int CX, int TW, int TH, int PXT, int CCH>
__global__ void __launch_bounds__(256, 2) lstm_step(
    const float* __restrict__ xin,
    const float* __restrict__ hprev,
    const float* __restrict__ wp,     // packed [co][cin][tap][gate]
    const float* __restrict__ bias,
    float* __restrict__ cst,
    float* __restrict__ hout)
{
    constexpr int SROW = (TW + 2 + 3) & ~3;
    constexpr int SPLANE = (TH + 2) * SROW;
    constexpr int HWIN = (TH + 2) * (TW + 2);
    constexpr int TILES_X = 64 / TW;
    constexpr int NCH = CIN / CCH;
    constexpr int IN_FL = CCH * SPLANE;
    constexpr int W_FL = 8 * CCH * 36;
    constexpr int BUFSZ = IN_FL + W_FL;
    constexpr int ICNT = CCH * HWIN;
    constexpr int WCNT4 = W_FL / 4;
    constexpr int IR = (ICNT + 255) / 256;

    extern __shared__ float sbuf[];
    const int tid = threadIdx.x;
    const int tile = blockIdx.x;
    const int tx0 = (tile % TILES_X) * TW;
    const int ty0 = (tile / TILES_X) * TH;
    const int co_l = tid >> 5;
    const int l = tid & 31;
    const int py = l & 7;
    const int pxi = l >> 3;
    const int p0 = pxi * PXT;
    const int co0 = blockIdx.y << 3;
    const int co = co0 + co_l;

    const float4* __restrict__ wsrc = reinterpret_cast<const float4*>(wp);

    // ---- load chunk 0 ----
    {
        for (int idx = tid; idx < ICNT; idx += 256) {
            int cin_l = idx / HWIN;
            int r = idx - cin_l * HWIN;
            int ly = r / (TW + 2);
            int lx = r - ly * (TW + 2);
            int gy = ty0 + ly - 1;
            int gx = tx0 + lx - 1;
            float v = 0.0f;
            if ((unsigned)gy < 64u && (unsigned)gx < 64u) {
                const float* src = (cin_l < CX) ? (xin + cin_l * NPIX)
                                                : (hprev + (cin_l - CX) * NPIX);
                v = src[gy * 64 + gx];
            }
            sbuf[cin_l * SPLANE + ly * SROW + lx] = v;
        }
        for (int d = tid; d < WCNT4; d += 256) {
            int cl_co = d / (CCH * 9);
            int rr = d - cl_co * (CCH * 9);
            const float4* g = wsrc + ((size_t)(co0 + cl_co) * CIN) * 9 + rr;
            cp16(smem_u32(reinterpret_cast<float4*>(sbuf + IN_FL) + d), g);
        }
        cp_commit();
        cp_wait0();
    }
    __syncthreads();

    ull acc0[PXT], acc1[PXT];
    {
        ull b0 = pack2(bias[0 * HC + co], bias[1 * HC + co]);
        ull b1 = pack2(bias[2 * HC + co], bias[3 * HC + co]);
#pragma unroll
        for (int j = 0; j < PXT; ++j) { acc0[j] = b0; acc1[j] = b1; }
    }

    for (int ch = 0; ch < NCH; ++ch) {
        float* buf = sbuf + ((NCH > 1) ? (ch & 1) * BUFSZ : 0);
        float* nbuf = sbuf + ((NCH > 1) ? ((ch + 1) & 1) * BUFSZ : 0);
        const bool pf = (NCH > 1) && (ch + 1 < NCH);

        // prefetch next chunk: weights via cp.async, input into registers
        float ist[IR];
        if (pf) {
            const int cin0n = (ch + 1) * CCH;
#pragma unroll
            for (int r = 0; r < IR; ++r) {
                int idx = tid + r * 256;
                float v = 0.0f;
                if (idx < ICNT) {
                    int cin_l = idx / HWIN;
                    int rr = idx - cin_l * HWIN;
                    int ly = rr / (TW + 2);
                    int lx = rr - ly * (TW + 2);
                    int gy = ty0 + ly - 1;
                    int gx = tx0 + lx - 1;
                    if ((unsigned)gy < 64u && (unsigned)gx < 64u) {
                        int ac = cin0n + cin_l;
                        const float* src = (ac < CX)
                            ? (xin + ac * NPIX)
                            : (hprev + (ac - CX) * NPIX);
                        v = src[gy * 64 + gx];
                    }
                }
                ist[r] = v;
            }
            for (int d = tid; d < WCNT4; d += 256) {
                int cl_co = d / (CCH * 9);
                int rr = d - cl_co * (CCH * 9);
                const float4* g = wsrc +
                    ((size_t)(co0 + cl_co) * CIN + cin0n) * 9 + rr;
                cp16(smem_u32(reinterpret_cast<float4*>(nbuf + IN_FL) + d), g);
            }
            cp_commit();
        }

        // ---- compute on current buffer (unroll 2: overlap LDS with FMA) ----
        const float* wbase = buf + IN_FL + co_l * (CCH * 36);
        const float* sb = buf + py * SROW + p0;
#pragma unroll 2
        for (int cl = 0; cl < CCH; ++cl) {
            const float* sr = sb + cl * SPLANE;
            const ulonglong2* wc =
                reinterpret_cast<const ulonglong2*>(wbase + cl * 36);

            ull in2[3][PXT + 2];
#pragma unroll
            for (int ky = 0; ky < 3; ++ky) {
                if (PXT == 4) {
                    float4 a = *reinterpret_cast<const float4*>(sr + ky * SROW);
                    float4 b = *reinterpret_cast<const float4*>(sr + ky * SROW + 4);
                    in2[ky][0] = dup2(a.x); in2[ky][1] = dup2(a.y);
                    in2[ky][2] = dup2(a.z); in2[ky][3] = dup2(a.w);
                    in2[ky][4] = dup2(b.x); in2[ky][5] = dup2(b.y);
                } else {
                    float2 a = *reinterpret_cast<const float2*>(sr + ky * SROW);
                    float2 b = *reinterpret_cast<const float2*>(sr + ky * SROW + 2);
                    in2[ky][0] = dup2(a.x); in2[ky][1] = dup2(a.y);
                    in2[ky][2] = dup2(b.x); in2[ky][3] = dup2(b.y);
                }
            }
#pragma unroll
            for (int ky = 0; ky < 3; ++ky) {
                // row-staged weight reads: 3 broadcast LDS.128 per row
                ulonglong2 w0 = wc[ky * 3 + 0];
                ulonglong2 w1 = wc[ky * 3 + 1];
                ulonglong2 w2 = wc[ky * 3 + 2];
#pragma unroll
                for (int j = 0; j < PXT; ++j) {
                    acc0[j] = ffma2(in2[ky][0 + j], w0.x, acc0[j]);
                    acc1[j] = ffma2(in2[ky][0 + j], w0.y, acc1[j]);
                    acc0[j] = ffma2(in2[ky][1 + j], w1.x, acc0[j]);
                    acc1[j] = ffma2(in2[ky][1 + j], w1.y, acc1[j]);
                    acc0[j] = ffma2(in2[ky][2 + j], w2.x, acc0[j]);
                    acc1[j] = ffma2(in2[ky][2 + j], w2.y, acc1[j]);
                }
            }
        }

        if (pf) {
            cp_wait0();
#pragma unroll
            for (int r = 0; r < IR; ++r) {
                int idx = tid + r * 256;
                if (idx < ICNT) {
                    int cin_l = idx / HWIN;
                    int rr = idx - cin_l * HWIN;
                    int ly = rr / (TW + 2);
                    int lx = rr - ly * (TW + 2);
                    nbuf[cin_l * SPLANE + ly * SROW + lx] = ist[r];
                }
            }
        }
        if (NCH > 1) __syncthreads();
    }

    // ---- epilogue ----
    const int gy = ty0 + py;
    const int base = co * NPIX + gy * 64 + tx0 + p0;
    float cold[4], cn[4], hv[4];
    if (PXT == 4) {
        float4 cv = *reinterpret_cast<const float4*>(cst + base);
        cold[0] = cv.x; cold[1] = cv.y; cold[2] = cv.z; cold[3] = cv.w;
    } else {
        float2 cv = *reinterpret_cast<const float2*>(cst + base);
        cold[0] = cv.x; cold[1] = cv.y;
    }
#pragma unroll
    for (int j = 0; j < PXT; ++j) {
        float zi, zf, zo, zg;
        unpack2(acc0[j], zi, zf);
        unpack2(acc1[j], zo, zg);
        float ig = sigmf(zi);
        float fg = sigmf(zf);
        float og = sigmf(zo);
        float gg = tanh_f(zg);
        float c = fmaf(fg, cold[j], ig * gg);
        cn[j] = c;
        hv[j] = og * tanh_f(c);
    }
    if (PXT == 4) {
        *reinterpret_cast<float4*>(cst + base) =
            make_float4(cn[0], cn[1], cn[2], cn[3]);
        *reinterpret_cast<float4*>(hout + base) =
            make_float4(hv[0], hv[1], hv[2], hv[3]);
    } else {
        *reinterpret_cast<float2*>(cst + base) = make_float2(cn[0], cn[1]);
        *reinterpret_cast<float2*>(hout + base) = make_float2(hv[0], hv[1]);
    }
}

// ----- FC pass 1: k-chunk partials -----
__global__ void __launch_bounds__(256) fc_part(const float* __restrict__ ys2,
                                               const float* __restrict__ fw,
                                               float* __restrict__ part) {
    __shared__ float red[8][6];
    const int kc = blockIdx.x;
    const int tid = threadIdx.x;
    const int lane = tid & 31;
    const int warp = tid >> 5;
    const int k0 = kc * 4096;
    const int NK = 64 * NPIX;

    for (int t = 0; t < TT; ++t) {
        const float* y = ys2 + (size_t)t * NK + k0;
        float acc[6] = {0.f, 0.f, 0.f, 0.f, 0.f, 0.f};
#pragma unroll 4
        for (int k = tid; k < 4096; k += 256) {
            float v = y[k];
#pragma unroll
            for (int j = 0; j < 6; ++j)
                acc[j] = fmaf(v, fw[(size_t)j * NK + k0 + k], acc[j]);
        }
#pragma unroll
        for (int j = 0; j < 6; ++j) {
#pragma unroll
            for (int off = 16; off > 0; off >>= 1)
                acc[j] += __shfl_xor_sync(0xffffffffu, acc[j], off);
        }
        if (lane < 6) red[warp][lane] = acc[lane];
        __syncthreads();
        if (tid < 6) {
            float s = 0.0f;
#pragma unroll
            for (int w = 0; w < 8; ++w) s += red[w][tid];
            part[(kc * TT + t) * 6 + tid] = s;
        }
        __syncthreads();
    }
}

// ----- FC pass 2 -----
__global__ void fc_reduce(const float* __restrict__ part,
                          const float* __restrict__ fb,
                          float* __restrict__ out) {
    int i = blockIdx.x * blockDim.x + threadIdx.x;
    if (i >= TT * 6) return;
    int j = i % 6;
    float s = fb[j];
    for (int kc = 0; kc < 64; ++kc) s += part[kc * TT * 6 + i];
    out[i] = s;
}

// ----- pack final states -----
__global__ void finalize_kernel(const float* __restrict__ ys1,
                                const float* __restrict__ c1,
                                const float* __restrict__ ys2,
                                const float* __restrict__ c2,
                                float* __restrict__ out) {
    int i = blockIdx.x * blockDim.x + threadIdx.x;
    const int N1 = 32 * NPIX;
    const int N2 = 64 * NPIX;
    if (i < N1) {
        out[768 + i] = ys1[(size_t)(TT - 1) * N1 + i];
    } else if (i < 2 * N1) {
        out[768 + i] = c1[i - N1];
    } else if (i < 2 * N1 + N2) {
        out[768 + i] = ys2[(size_t)(TT - 1) * N2 + (i - 2 * N1)];
    } else if (i < 2 * N1 + 2 * N2) {
        out[768 + i] = c2[i - 2 * N1 - N2];
    }
}

extern "C" void kernel_launch(void* const* d_in, const int* in_sizes, int n_in,
                              void* d_out, int out_size) {
    const float* input = (const float*)d_in[0];
    const float* w1    = (const float*)d_in[1];
    const float* b1    = (const float*)d_in[2];
    const float* w2    = (const float*)d_in[3];
    const float* b2    = (const float*)d_in[4];
    const float* fcw   = (const float*)d_in[5];
    const float* fcb   = (const float*)d_in[6];
    float* out = (float*)d_out;

    float *ys1, *ys2, *c1, *c2, *zb, *w1p, *w2p, *fcpart;
    cudaGetSymbolAddress((void**)&ys1, g_ys1);
    cudaGetSymbolAddress((void**)&ys2, g_ys2);
    cudaGetSymbolAddress((void**)&c1, g_c1);
    cudaGetSymbolAddress((void**)&c2, g_c2);
    cudaGetSymbolAddress((void**)&zb, g_zerobuf);
    cudaGetSymbolAddress((void**)&w1p, g_w1p);
    cudaGetSymbolAddress((void**)&w2p, g_w2p);
    cudaGetSymbolAddress((void**)&fcpart, g_fcpart);

    const int sm1 = (35 * 120 + 8 * 35 * 36) * 4;
    const int sm2 = 2 * (16 * 200 + 8 * 16 * 36) * 4;
    cudaFuncSetAttribute((const void*)lstm_step<32, 35, 3, 8, 8, 2, 35>,
                         cudaFuncAttributeMaxDynamicSharedMemorySize, sm1);
    cudaFuncSetAttribute((const void*)lstm_step<64, 96, 32, 16, 8, 4, 16>,
                         cudaFuncAttributeMaxDynamicSharedMemorySize, sm2);

    const int NSETUP = 32 * NPIX + 3 * 64 * NPIX + 32 * 35 * 36 + 64 * 96 * 36;
    setup_kernel<<<(NSETUP + 255) / 256, 256>>>(w1, w2, w1p, w2p, c1, c2, zb);

    dim3 blk(256);
    dim3 g1(64, 4);
    dim3 g2(32, 8);

    for (int t = 0; t < TT; ++t) {
        const float* x1 = input + (size_t)t * 3 * NPIX;
        const float* hp1 = (t == 0) ? zb : (ys1 + (size_t)(t - 1) * 32 * NPIX);
        float* ho1 = ys1 + (size_t)t * 32 * NPIX;
        lstm_step<32, 35, 3, 8, 8, 2, 35><<<g1, blk, sm1>>>(
            x1, hp1, w1p, b1, c1, ho1);

        const float* x2 = ys1 + (size_t)t * 32 * NPIX;
        const float* hp2 = (t == 0) ? zb : (ys2 + (size_t)(t - 1) * 64 * NPIX);
        float* ho2 = ys2 + (size_t)t * 64 * NPIX;
        lstm_step<64, 96, 32, 16, 8, 4, 16><<<g2, blk, sm2>>>(
            x2, hp2, w2p, b2, c2, ho2);
    }

    fc_part<<<64, 256>>>(ys2, fcw, fcpart);
    fc_reduce<<<3, 256>>>(fcpart, fcb, out);

    const int NFIN = 2 * 32 * NPIX + 2 * 64 * NPIX;
    finalize_kernel<<<(NFIN + 255) / 256, 256>>>(ys1, c1, ys2, c2, out);
}

// round 7
// speedup vs baseline: 1.0900x; 1.0900x over previous
#include <cuda_runtime.h>
#include <math.h>

// ---------------------------------------------------------------------------
// PoseConvLSTM, R7: fused step kernel — blocks [0,512) compute L2[t],
// blocks [512,768) compute L1[t+1] (independent given ys1[t]). Both layers
// share the chip -> higher warp occupancy; launch count 258 -> 131.
// fp32 with packed fma.rn.f32x2 (FFMA2), smem-staged weights.
// ---------------------------------------------------------------------------

#define NPIX 4096
#define TT 128

typedef unsigned long long ull;

// ----- scratch -----
__device__ float g_ys1[TT * 32 * NPIX];
__device__ float g_ys2[TT * 64 * NPIX];
__device__ float g_c1[32 * NPIX];
__device__ float g_c2[64 * NPIX];
__device__ float g_zerobuf[64 * NPIX];
__device__ __align__(16) float g_w1p[32 * 35 * 36];
__device__ __align__(16) float g_w2p[64 * 96 * 36];
__device__ float g_fcpart[64 * TT * 6];

__device__ __forceinline__ float sigmf(float x) {
    return 1.0f / (1.0f + __expf(-x));
}
__device__ __forceinline__ float tanh_f(float x) {
    return 1.0f - 2.0f / (__expf(2.0f * x) + 1.0f);
}

// ----- f32x2 helpers -----
__device__ __forceinline__ ull pack2(float lo, float hi) {
    ull r;
    asm("mov.b64 %0, {%1, %2};" : "=l"(r) : "f"(lo), "f"(hi));
    return r;
}
__device__ __forceinline__ ull dup2(float v) {
    ull r;
    asm("mov.b64 %0, {%1, %1};" : "=l"(r) : "f"(v));
    return r;
}
__device__ __forceinline__ void unpack2(ull p, float& lo, float& hi) {
    asm("mov.b64 {%0, %1}, %2;" : "=f"(lo), "=f"(hi) : "l"(p));
}
__device__ __forceinline__ ull ffma2(ull a, ull b, ull c) {
    ull d;
    asm("fma.rn.f32x2 %0, %1, %2, %3;" : "=l"(d) : "l"(a), "l"(b), "l"(c));
    return d;
}
__device__ __forceinline__ unsigned smem_u32(const void* p) {
    return (unsigned)__cvta_generic_to_shared(p);
}
__device__ __forceinline__ void cp16(unsigned s, const void* g) {
    asm volatile("cp.async.cg.shared.global [%0], [%1], 16;"
                 :: "r"(s), "l"(g) : "memory");
}
__device__ __forceinline__ void cp_commit() {
    asm volatile("cp.async.commit_group;" ::: "memory");
}
__device__ __forceinline__ void cp_wait0() {
    asm volatile("cp.async.wait_group 0;" ::: "memory");
}

// ----- merged setup (1 launch) -----
__global__ void setup_kernel(const float* __restrict__ w1,
                             const float* __restrict__ w2,
                             float* __restrict__ w1p, float* __restrict__ w2p,
                             float* __restrict__ c1, float* __restrict__ c2,
                             float* __restrict__ zb) {
    int i = blockIdx.x * blockDim.x + threadIdx.x;
    const int N_C1 = 32 * NPIX;
    const int N_C2 = 64 * NPIX;
    const int N_W1 = 32 * 35 * 36;
    const int N_W2 = 64 * 96 * 36;
    if (i < N_C1) { c1[i] = 0.0f; return; }
    i -= N_C1;
    if (i < N_C2) { c2[i] = 0.0f; return; }
    i -= N_C2;
    if (i < N_C2) { zb[i] = 0.0f; return; }
    i -= N_C2;
    if (i < N_W1) {
        int g = i & 3; int r = i >> 2;
        int t = r % 9; r /= 9;
        int cin = r % 35; int co = r / 35;
        w1p[i] = w1[((g * 32 + co) * 35 + cin) * 9 + t];
        return;
    }
    i -= N_W1;
    if (i < N_W2) {
        int g = i & 3; int r = i >> 2;
        int t = r % 9; r /= 9;
        int cin = r % 96; int co = r / 96;
        w2p[i] = w2[((g * 64 + co) * 96 + cin) * 9 + t];
        return;
    }
}

// ----- ConvLSTM step body (device fn; 8x8 tile, PXT=2, 8 co per block) ----
// bx in [0, 64*HC/8): tile = bx % 64, cogroup = bx / 64
template <int HC, int CIN, int CX, int CCH>
__device__ __forceinline__ void lstm_body(
    int bx, float* sbuf,
    const float* __restrict__ xin,
    const float* __restrict__ hprev,
    const float* __restrict__ wp,
    const float* __restrict__ bias,
    float* __restrict__ cst,
    float* __restrict__ hout)
{
    constexpr int TW = 8, TH = 8, PXT = 2;
    constexpr int SROW = 12;
    constexpr int SPLANE = (TH + 2) * SROW;        // 120
    constexpr int HWIN = (TH + 2) * (TW + 2);      // 100
    constexpr int NCH = CIN / CCH;
    constexpr int IN_FL = CCH * SPLANE;
    constexpr int W_FL = 8 * CCH * 36;
    constexpr int BUFSZ = IN_FL + W_FL;
    constexpr int ICNT = CCH * HWIN;
    constexpr int WCNT4 = W_FL / 4;
    constexpr int IR = (ICNT + 255) / 256;

    const int tid = threadIdx.x;
    const int tile = bx & 63;
    const int cog = bx >> 6;
    const int tx0 = (tile & 7) * TW;
    const int ty0 = (tile >> 3) * TH;
    const int co_l = tid >> 5;
    const int l = tid & 31;
    const int py = l & 7;
    const int pxi = l >> 3;
    const int p0 = pxi * PXT;
    const int co0 = cog << 3;
    const int co = co0 + co_l;

    const float4* __restrict__ wsrc = reinterpret_cast<const float4*>(wp);

    // ---- load chunk 0 ----
    for (int idx = tid; idx < ICNT; idx += 256) {
        int cin_l = idx / HWIN;
        int r = idx - cin_l * HWIN;
        int ly = r / (TW + 2);
        int lx = r - ly * (TW + 2);
        int gy = ty0 + ly - 1;
        int gx = tx0 + lx - 1;
        float v = 0.0f;
        if ((unsigned)gy < 64u && (unsigned)gx < 64u) {
            const float* src = (cin_l < CX) ? (xin + cin_l * NPIX)
                                            : (hprev + (cin_l - CX) * NPIX);
            v = src[gy * 64 + gx];
        }
        sbuf[cin_l * SPLANE + ly * SROW + lx] = v;
    }
    for (int d = tid; d < WCNT4; d += 256) {
        int cl_co = d / (CCH * 9);
        int rr = d - cl_co * (CCH * 9);
        const float4* g = wsrc + ((size_t)(co0 + cl_co) * CIN) * 9 + rr;
        cp16(smem_u32(reinterpret_cast<float4*>(sbuf + IN_FL) + d), g);
    }
    cp_commit();
    cp_wait0();
    __syncthreads();

    ull acc0[PXT], acc1[PXT];
    {
        ull b0 = pack2(bias[0 * HC + co], bias[1 * HC + co]);
        ull b1 = pack2(bias[2 * HC + co], bias[3 * HC + co]);
#pragma unroll
        for (int j = 0; j < PXT; ++j) { acc0[j] = b0; acc1[j] = b1; }
    }

    for (int ch = 0; ch < NCH; ++ch) {
        float* buf = sbuf + ((NCH > 1) ? (ch & 1) * BUFSZ : 0);
        float* nbuf = sbuf + ((NCH > 1) ? ((ch + 1) & 1) * BUFSZ : 0);
        const bool pf = (NCH > 1) && (ch + 1 < NCH);

        float ist[IR];
        if (pf) {
            const int cin0n = (ch + 1) * CCH;
#pragma unroll
            for (int r = 0; r < IR; ++r) {
                int idx = tid + r * 256;
                float v = 0.0f;
                if (idx < ICNT) {
                    int cin_l = idx / HWIN;
                    int rr = idx - cin_l * HWIN;
                    int ly = rr / (TW + 2);
                    int lx = rr - ly * (TW + 2);
                    int gy = ty0 + ly - 1;
                    int gx = tx0 + lx - 1;
                    if ((unsigned)gy < 64u && (unsigned)gx < 64u) {
                        int ac = cin0n + cin_l;
                        const float* src = (ac < CX)
                            ? (xin + ac * NPIX)
                            : (hprev + (ac - CX) * NPIX);
                        v = src[gy * 64 + gx];
                    }
                }
                ist[r] = v;
            }
            for (int d = tid; d < WCNT4; d += 256) {
                int cl_co = d / (CCH * 9);
                int rr = d - cl_co * (CCH * 9);
                const float4* g = wsrc +
                    ((size_t)(co0 + cl_co) * CIN + cin0n) * 9 + rr;
                cp16(smem_u32(reinterpret_cast<float4*>(nbuf + IN_FL) + d), g);
            }
            cp_commit();
        }

        // ---- compute on current buffer ----
        const float* wbase = buf + IN_FL + co_l * (CCH * 36);
        const float* sb = buf + py * SROW + p0;
#pragma unroll 1
        for (int cl = 0; cl < CCH; ++cl) {
            const float* sr = sb + cl * SPLANE;
            const ulonglong2* wc =
                reinterpret_cast<const ulonglong2*>(wbase + cl * 36);

            ull in2[3][4];
#pragma unroll
            for (int ky = 0; ky < 3; ++ky) {
                float2 a = *reinterpret_cast<const float2*>(sr + ky * SROW);
                float2 b = *reinterpret_cast<const float2*>(sr + ky * SROW + 2);
                in2[ky][0] = dup2(a.x); in2[ky][1] = dup2(a.y);
                in2[ky][2] = dup2(b.x); in2[ky][3] = dup2(b.y);
            }
#pragma unroll
            for (int ky = 0; ky < 3; ++ky) {
                ulonglong2 w0 = wc[ky * 3 + 0];
                ulonglong2 w1 = wc[ky * 3 + 1];
                ulonglong2 w2 = wc[ky * 3 + 2];
#pragma unroll
                for (int j = 0; j < PXT; ++j) {
                    acc0[j] = ffma2(in2[ky][0 + j], w0.x, acc0[j]);
                    acc1[j] = ffma2(in2[ky][0 + j], w0.y, acc1[j]);
                    acc0[j] = ffma2(in2[ky][1 + j], w1.x, acc0[j]);
                    acc1[j] = ffma2(in2[ky][1 + j], w1.y, acc1[j]);
                    acc0[j] = ffma2(in2[ky][2 + j], w2.x, acc0[j]);
                    acc1[j] = ffma2(in2[ky][2 + j], w2.y, acc1[j]);
                }
            }
        }

        if (pf) {
            cp_wait0();
#pragma unroll
            for (int r = 0; r < IR; ++r) {
                int idx = tid + r * 256;
                if (idx < ICNT) {
                    int cin_l = idx / HWIN;
                    int rr = idx - cin_l * HWIN;
                    int ly = rr / (TW + 2);
                    int lx = rr - ly * (TW + 2);
                    nbuf[cin_l * SPLANE + ly * SROW + lx] = ist[r];
                }
            }
        }
        if (NCH > 1) __syncthreads();
    }

    // ---- epilogue ----
    const int gy = ty0 + py;
    const int base = co * NPIX + gy * 64 + tx0 + p0;
    float2 cv = *reinterpret_cast<const float2*>(cst + base);
    float cold[2] = {cv.x, cv.y};
    float cn[2], hv[2];
#pragma unroll
    for (int j = 0; j < PXT; ++j) {
        float zi, zf, zo, zg;
        unpack2(acc0[j], zi, zf);
        unpack2(acc1[j], zo, zg);
        float ig = sigmf(zi);
        float fg = sigmf(zf);
        float og = sigmf(zo);
        float gg = tanh_f(zg);
        float c = fmaf(fg, cold[j], ig * gg);
        cn[j] = c;
        hv[j] = og * tanh_f(c);
    }
    *reinterpret_cast<float2*>(cst + base) = make_float2(cn[0], cn[1]);
    *reinterpret_cast<float2*>(hout + base) = make_float2(hv[0], hv[1]);
}

// ----- standalone step kernels (t=0 L1, t=127 L2) -----
template <int HC, int CIN, int CX, int CCH>
__global__ void __launch_bounds__(256, 3) lstm_step(
    const float* __restrict__ xin, const float* __restrict__ hprev,
    const float* __restrict__ wp, const float* __restrict__ bias,
    float* __restrict__ cst, float* __restrict__ hout)
{
    extern __shared__ float sbuf[];
    lstm_body<HC, CIN, CX, CCH>(blockIdx.x, sbuf, xin, hprev, wp, bias,
                                cst, hout);
}

// ----- fused: blocks [0,512) = L2[t]; [512,768) = L1[t+1] -----
__global__ void __launch_bounds__(256, 3) fused_step(
    const float* __restrict__ ys1_t,     // [32,64,64] (L2 x-input, L1 hprev)
    const float* __restrict__ ys2_prev,  // [64,64,64]
    const float* __restrict__ w2p, const float* __restrict__ b2,
    float* __restrict__ c2, float* __restrict__ ys2_t,
    const float* __restrict__ x_next,    // [3,64,64]
    const float* __restrict__ w1p, const float* __restrict__ b1,
    float* __restrict__ c1, float* __restrict__ ys1_next)
{
    extern __shared__ float sbuf[];
    int bx = blockIdx.x;
    if (bx < 512) {
        lstm_body<64, 96, 32, 16>(bx, sbuf, ys1_t, ys2_prev, w2p, b2,
                                  c2, ys2_t);
    } else {
        lstm_body<32, 35, 3, 35>(bx - 512, sbuf, x_next, ys1_t, w1p, b1,
                                 c1, ys1_next);
    }
}

// ----- FC pass 1: k-chunk partials -----
__global__ void __launch_bounds__(256) fc_part(const float* __restrict__ ys2,
                                               const float* __restrict__ fw,
                                               float* __restrict__ part) {
    __shared__ float red[8][6];
    const int kc = blockIdx.x;
    const int tid = threadIdx.x;
    const int lane = tid & 31;
    const int warp = tid >> 5;
    const int k0 = kc * 4096;
    const int NK = 64 * NPIX;

    for (int t = 0; t < TT; ++t) {
        const float* y = ys2 + (size_t)t * NK + k0;
        float acc[6] = {0.f, 0.f, 0.f, 0.f, 0.f, 0.f};
#pragma unroll 4
        for (int k = tid; k < 4096; k += 256) {
            float v = y[k];
#pragma unroll
            for (int j = 0; j < 6; ++j)
                acc[j] = fmaf(v, fw[(size_t)j * NK + k0 + k], acc[j]);
        }
#pragma unroll
        for (int j = 0; j < 6; ++j) {
#pragma unroll
            for (int off = 16; off > 0; off >>= 1)
                acc[j] += __shfl_xor_sync(0xffffffffu, acc[j], off);
        }
        if (lane < 6) red[warp][lane] = acc[lane];
        __syncthreads();
        if (tid < 6) {
            float s = 0.0f;
#pragma unroll
            for (int w = 0; w < 8; ++w) s += red[w][tid];
            part[(kc * TT + t) * 6 + tid] = s;
        }
        __syncthreads();
    }
}

// ----- FC pass 2 -----
__global__ void fc_reduce(const float* __restrict__ part,
                          const float* __restrict__ fb,
                          float* __restrict__ out) {
    int i = blockIdx.x * blockDim.x + threadIdx.x;
    if (i >= TT * 6) return;
    int j = i % 6;
    float s = fb[j];
    for (int kc = 0; kc < 64; ++kc) s += part[kc * TT * 6 + i];
    out[i] = s;
}

// ----- pack final states -----
__global__ void finalize_kernel(const float* __restrict__ ys1,
                                const float* __restrict__ c1,
                                const float* __restrict__ ys2,
                                const float* __restrict__ c2,
                                float* __restrict__ out) {
    int i = blockIdx.x * blockDim.x + threadIdx.x;
    const int N1 = 32 * NPIX;
    const int N2 = 64 * NPIX;
    if (i < N1) {
        out[768 + i] = ys1[(size_t)(TT - 1) * N1 + i];
    } else if (i < 2 * N1) {
        out[768 + i] = c1[i - N1];
    } else if (i < 2 * N1 + N2) {
        out[768 + i] = ys2[(size_t)(TT - 1) * N2 + (i - 2 * N1)];
    } else if (i < 2 * N1 + 2 * N2) {
        out[768 + i] = c2[i - 2 * N1 - N2];
    }
}

extern "C" void kernel_launch(void* const* d_in, const int* in_sizes, int n_in,
                              void* d_out, int out_size) {
    const float* input = (const float*)d_in[0];
    const float* w1    = (const float*)d_in[1];
    const float* b1    = (const float*)d_in[2];
    const float* w2    = (const float*)d_in[3];
    const float* b2    = (const float*)d_in[4];
    const float* fcw   = (const float*)d_in[5];
    const float* fcb   = (const float*)d_in[6];
    float* out = (float*)d_out;

    float *ys1, *ys2, *c1, *c2, *zb, *w1p, *w2p, *fcpart;
    cudaGetSymbolAddress((void**)&ys1, g_ys1);
    cudaGetSymbolAddress((void**)&ys2, g_ys2);
    cudaGetSymbolAddress((void**)&c1, g_c1);
    cudaGetSymbolAddress((void**)&c2, g_c2);
    cudaGetSymbolAddress((void**)&zb, g_zerobuf);
    cudaGetSymbolAddress((void**)&w1p, g_w1p);
    cudaGetSymbolAddress((void**)&w2p, g_w2p);
    cudaGetSymbolAddress((void**)&fcpart, g_fcpart);

    // L1 (CCH=35, single chunk): (35*120 + 8*35*36)*4 = 57120 B
    // L2 (CCH=16, double buf):   2*(16*120 + 8*16*36)*4 = 52224 B
    const int smL1 = (35 * 120 + 8 * 35 * 36) * 4;       // 57120
    const int smL2 = 2 * (16 * 120 + 8 * 16 * 36) * 4;   // 52224
    const int smF = smL1 > smL2 ? smL1 : smL2;
    cudaFuncSetAttribute((const void*)lstm_step<32, 35, 3, 35>,
                         cudaFuncAttributeMaxDynamicSharedMemorySize, smL1);
    cudaFuncSetAttribute((const void*)lstm_step<64, 96, 32, 16>,
                         cudaFuncAttributeMaxDynamicSharedMemorySize, smL2);
    cudaFuncSetAttribute((const void*)fused_step,
                         cudaFuncAttributeMaxDynamicSharedMemorySize, smF);

    const int NSETUP = 32 * NPIX + 3 * 64 * NPIX + 32 * 35 * 36 + 64 * 96 * 36;
    setup_kernel<<<(NSETUP + 255) / 256, 256>>>(w1, w2, w1p, w2p, c1, c2, zb);

    // t = 0 layer 1 (h0 = 0)
    lstm_step<32, 35, 3, 35><<<256, 256, smL1>>>(input, zb, w1p, b1, c1, ys1);

    // fused steps: L2[t] + L1[t+1], t = 0..126
    for (int t = 0; t < TT - 1; ++t) {
        const float* y1t = ys1 + (size_t)t * 32 * NPIX;
        const float* y2p = (t == 0) ? zb : (ys2 + (size_t)(t - 1) * 64 * NPIX);
        float* y2t = ys2 + (size_t)t * 64 * NPIX;
        const float* xn = input + (size_t)(t + 1) * 3 * NPIX;
        float* y1n = ys1 + (size_t)(t + 1) * 32 * NPIX;
        fused_step<<<768, 256, smF>>>(y1t, y2p, w2p, b2, c2, y2t,
                                      xn, w1p, b1, c1, y1n);
    }

    // t = 127 layer 2
    lstm_step<64, 96, 32, 16><<<512, 256, smL2>>>(
        ys1 + (size_t)(TT - 1) * 32 * NPIX,
        ys2 + (size_t)(TT - 2) * 64 * NPIX,
        w2p, b2, c2, ys2 + (size_t)(TT - 1) * 64 * NPIX);

    fc_part<<<64, 256>>>(ys2, fcw, fcpart);
    fc_reduce<<<3, 256>>>(fcpart, fcb, out);

    const int NFIN = 2 * 32 * NPIX + 2 * 64 * NPIX;
    finalize_kernel<<<(NFIN + 255) / 256, 256>>>(ys1, c1, ys2, c2, out);
}